// round 1
// baseline (speedup 1.0000x reference)
#include <cuda_runtime.h>

typedef unsigned long long ULL;

#define N_NODES 50000
#define NNB     16
#define DIN     128
#define EDIM    64
#define DOUT    128
#define K1      (DIN + EDIM)    // 192
#define K2      (DIN + DOUT)    // 256
#define NB      32              // nodes per CTA
#define TPB     256
#define XS1     (K1 + 2)        // per-node x row stride in f32x2 units (bank-spread pad)
#define XS2     (K2 + 2)

// Scratch (allocation-free rule: __device__ globals)
__device__ float g_Wt_msg[K1 * DOUT];                 // [k][o]
__device__ float g_Wt_apply[K2 * DOUT];               // [k][o]
__device__ float g_hneigh[(size_t)N_NODES * DOUT];

__device__ __forceinline__ ULL fma2(ULL a, ULL b, ULL c) {
    ULL d;
    asm("fma.rn.f32x2 %0, %1, %2, %3;" : "=l"(d) : "l"(a), "l"(b), "l"(c));
    return d;
}

__device__ __forceinline__ float2 unpack2(ULL a) {
    unsigned lo, hi;
    asm("mov.b64 {%0, %1}, %2;" : "=r"(lo), "=r"(hi) : "l"(a));
    return make_float2(__uint_as_float(lo), __uint_as_float(hi));
}

// One-time (per replay, cheap) weight transpose into [k][o] layout so every CTA
// can copy weights into smem fully coalesced + conflict-free.
__global__ void transpose_kernel(const float* __restrict__ Wm,
                                 const float* __restrict__ Wa) {
    int i = blockIdx.x * blockDim.x + threadIdx.x;
    if (i < DOUT * K1) {
        int o = i / K1, k = i - o * K1;
        g_Wt_msg[k * DOUT + o] = Wm[i];
    }
    if (i < DOUT * K2) {
        int o = i / K2, k = i - o * K2;
        g_Wt_apply[k * DOUT + o] = Wa[i];
    }
}

// f32x2 dual-node GEMV core.
// Thread (og, ng) computes outputs o = 2*(og+16p)+{0,1}, p=0..3, for local nodes
// {2ng, 2ng+1}. Weight smem wt2[k*64 + op] holds {W[2op][k], W[2op+1][k]} — per k
// the 16 lanes (og) read 16 consecutive 64-bit words = one 128B conflict-free line.
// x smem is stored duplicated ({v,v}) so no per-iteration packing MOVs are needed.
template <int K, int XS>
__device__ __forceinline__ void gemv_dual(const ULL* __restrict__ wt2,
                                          const ULL* __restrict__ xs2,
                                          int og, int ng,
                                          ULL acc0[4], ULL acc1[4]) {
    const ULL* xa = xs2 + (2 * ng) * XS;
    const ULL* xb = xa + XS;
    const ULL* w  = wt2 + og;
#pragma unroll 8
    for (int k = 0; k < K; ++k) {
        ULL x0 = xa[k];
        ULL x1 = xb[k];
#pragma unroll
        for (int p = 0; p < 4; ++p) {
            ULL ww = w[k * 64 + 16 * p];
            acc0[p] = fma2(ww, x0, acc0[p]);
            acc1[p] = fma2(ww, x1, acc1[p]);
        }
    }
}

// Kernel 1: gather-sum neighbors + edge feats, then h_neigh = W_msg@[s;es]/16 + b_msg
__global__ void __launch_bounds__(TPB)
msg_kernel(const float* __restrict__ nfeats, const float* __restrict__ efeats,
           const float* __restrict__ b_msg, const int* __restrict__ src_idx) {
    extern __shared__ ULL smem[];
    ULL* wt2 = smem;                 // K1*64 f32x2
    ULL* xs2 = smem + K1 * 64;       // NB rows of XS1 f32x2 (duplicated x)

    const int tid  = threadIdx.x;
    const int base = blockIdx.x * NB;

    // coalesced, conflict-free weight stage-in (98 KB)
    {
        const float4* s = (const float4*)g_Wt_msg;
        float4*       d = (float4*)wt2;
#pragma unroll
        for (int i = 0; i < (K1 * DOUT / 4) / TPB; ++i)
            d[tid + i * TPB] = s[tid + i * TPB];
    }

    // gather phase: each warp owns 4 nodes; lane = float4 slot of the 128-dim row
    const int warp = tid >> 5, lane = tid & 31;
#pragma unroll
    for (int q = 0; q < 4; ++q) {
        int nd   = warp * 4 + q;
        int node = base + nd;
        if (node < N_NODES) {
            float4 aS = make_float4(0.f, 0.f, 0.f, 0.f);
            float4 aE = make_float4(0.f, 0.f, 0.f, 0.f);
            const int*    ip = src_idx + node * NNB;
            const float4* ef = (const float4*)(efeats + (size_t)node * NNB * EDIM);
#pragma unroll 4
            for (int j = 0; j < NNB; ++j) {
                int s = __ldg(ip + j);
                float4 a = __ldg((const float4*)nfeats + (size_t)s * (DIN / 4) + lane);
                aS.x += a.x; aS.y += a.y; aS.z += a.z; aS.w += a.w;
                if (lane < EDIM / 4) {
                    float4 b = __ldg(ef + j * (EDIM / 4) + lane);
                    aE.x += b.x; aE.y += b.y; aE.z += b.z; aE.w += b.w;
                }
            }
            const float inv = 1.f / 16.f;   // mean (cnt == 16 exactly, dst = repeat(arange,16))
            float2* xrow = (float2*)(xs2 + nd * XS1);
            int k0 = lane * 4;
            xrow[k0 + 0] = make_float2(aS.x * inv, aS.x * inv);
            xrow[k0 + 1] = make_float2(aS.y * inv, aS.y * inv);
            xrow[k0 + 2] = make_float2(aS.z * inv, aS.z * inv);
            xrow[k0 + 3] = make_float2(aS.w * inv, aS.w * inv);
            if (lane < EDIM / 4) {
                int ke = DIN + lane * 4;
                xrow[ke + 0] = make_float2(aE.x * inv, aE.x * inv);
                xrow[ke + 1] = make_float2(aE.y * inv, aE.y * inv);
                xrow[ke + 2] = make_float2(aE.z * inv, aE.z * inv);
                xrow[ke + 3] = make_float2(aE.w * inv, aE.w * inv);
            }
        }
    }
    __syncthreads();

    const int og = tid & 15, ng = tid >> 4;
    ULL acc0[4] = {0ull, 0ull, 0ull, 0ull};
    ULL acc1[4] = {0ull, 0ull, 0ull, 0ull};
    gemv_dual<K1, XS1>(wt2, xs2, og, ng, acc0, acc1);

    const float2* b2 = (const float2*)b_msg;
    int n0 = base + 2 * ng;
#pragma unroll
    for (int p = 0; p < 4; ++p) {
        int op = og + 16 * p;
        float2 bb = __ldg(b2 + op);
        if (n0 < N_NODES) {
            float2 v = unpack2(acc0[p]);
            v.x += bb.x; v.y += bb.y;
            ((float2*)(g_hneigh + (size_t)n0 * DOUT))[op] = v;
        }
        if (n0 + 1 < N_NODES) {
            float2 v = unpack2(acc1[p]);
            v.x += bb.x; v.y += bb.y;
            ((float2*)(g_hneigh + (size_t)(n0 + 1) * DOUT))[op] = v;
        }
    }
}

// Kernel 2: out = relu(W_apply @ [nfeats ; h_neigh] + b_apply)
__global__ void __launch_bounds__(TPB)
apply_kernel(const float* __restrict__ nfeats, const float* __restrict__ b_apply,
             float* __restrict__ out) {
    extern __shared__ ULL smem[];
    ULL* wt2 = smem;                 // K2*64
    ULL* xs2 = smem + K2 * 64;

    const int tid  = threadIdx.x;
    const int base = blockIdx.x * NB;

    {
        const float4* s = (const float4*)g_Wt_apply;
        float4*       d = (float4*)wt2;
#pragma unroll
        for (int i = 0; i < (K2 * DOUT / 4) / TPB; ++i)
            d[tid + i * TPB] = s[tid + i * TPB];
    }

    const int warp = tid >> 5, lane = tid & 31;
#pragma unroll
    for (int q = 0; q < 4; ++q) {
        int nd   = warp * 4 + q;
        int node = base + nd;
        if (node < N_NODES) {
            float4 a = __ldg((const float4*)(nfeats   + (size_t)node * DIN)  + lane);
            float4 h = __ldg((const float4*)(g_hneigh + (size_t)node * DOUT) + lane);
            float2* xrow = (float2*)(xs2 + nd * XS2);
            int k0 = lane * 4;
            xrow[k0 + 0] = make_float2(a.x, a.x);
            xrow[k0 + 1] = make_float2(a.y, a.y);
            xrow[k0 + 2] = make_float2(a.z, a.z);
            xrow[k0 + 3] = make_float2(a.w, a.w);
            int kh = DIN + lane * 4;
            xrow[kh + 0] = make_float2(h.x, h.x);
            xrow[kh + 1] = make_float2(h.y, h.y);
            xrow[kh + 2] = make_float2(h.z, h.z);
            xrow[kh + 3] = make_float2(h.w, h.w);
        }
    }
    __syncthreads();

    const int og = tid & 15, ng = tid >> 4;
    ULL acc0[4] = {0ull, 0ull, 0ull, 0ull};
    ULL acc1[4] = {0ull, 0ull, 0ull, 0ull};
    gemv_dual<K2, XS2>(wt2, xs2, og, ng, acc0, acc1);

    const float2* b2 = (const float2*)b_apply;
    int n0 = base + 2 * ng;
#pragma unroll
    for (int p = 0; p < 4; ++p) {
        int op = og + 16 * p;
        float2 bb = __ldg(b2 + op);
        if (n0 < N_NODES) {
            float2 v = unpack2(acc0[p]);
            v.x = fmaxf(v.x + bb.x, 0.f);
            v.y = fmaxf(v.y + bb.y, 0.f);
            ((float2*)(out + (size_t)n0 * DOUT))[op] = v;
        }
        if (n0 + 1 < N_NODES) {
            float2 v = unpack2(acc1[p]);
            v.x = fmaxf(v.x + bb.x, 0.f);
            v.y = fmaxf(v.y + bb.y, 0.f);
            ((float2*)(out + (size_t)(n0 + 1) * DOUT))[op] = v;
        }
    }
}

extern "C" void kernel_launch(void* const* d_in, const int* in_sizes, int n_in,
                              void* d_out, int out_size) {
    (void)in_sizes; (void)n_in; (void)out_size;
    const float* nfeats  = (const float*)d_in[0];
    const float* efeats  = (const float*)d_in[1];
    const float* W_msg   = (const float*)d_in[2];
    const float* b_msg   = (const float*)d_in[3];
    const float* W_apply = (const float*)d_in[4];
    const float* b_apply = (const float*)d_in[5];
    const int*   src_idx = (const int*)d_in[6];
    // d_in[7] = dst_idx: structurally repeat(arange(N),16) -> not needed
    float* out = (float*)d_out;

    const size_t smem1 = (size_t)(K1 * 64 + NB * XS1) * sizeof(ULL);  // 147,968 B
    const size_t smem2 = (size_t)(K2 * 64 + NB * XS2) * sizeof(ULL);  // 197,120 B
    cudaFuncSetAttribute(msg_kernel,   cudaFuncAttributeMaxDynamicSharedMemorySize, (int)smem1);
    cudaFuncSetAttribute(apply_kernel, cudaFuncAttributeMaxDynamicSharedMemorySize, (int)smem2);

    const int grid = (N_NODES + NB - 1) / NB;  // 1563
    transpose_kernel<<<(DOUT * K2 + TPB - 1) / TPB, TPB>>>(W_msg, W_apply);
    msg_kernel<<<grid, TPB, smem1>>>(nfeats, efeats, b_msg, src_idx);
    apply_kernel<<<grid, TPB, smem2>>>(nfeats, b_apply, out);
}

// round 2
// speedup vs baseline: 1.0005x; 1.0005x over previous
#include <cuda_runtime.h>

typedef unsigned long long ULL;

#define N_NODES 50000
#define NNB     16
#define DIN     128
#define EDIM    64
#define DOUT    128
#define K1      (DIN + EDIM)    // 192
#define K2      (DIN + DOUT)    // 256
#define NB      32              // nodes per CTA
#define TPB     256
#define XS1     (K1 + 2)        // per-node x row stride in f32x2 units (bank-spread pad)
#define XS2     (K2 + 2)

// Scratch (allocation-free rule: __device__ globals)
__device__ float g_Wt_msg[K1 * DOUT];                 // [k][o]
__device__ float g_Wt_apply[K2 * DOUT];               // [k][o]
__device__ float g_hneigh[(size_t)N_NODES * DOUT];

__device__ __forceinline__ ULL fma2(ULL a, ULL b, ULL c) {
    ULL d;
    asm("fma.rn.f32x2 %0, %1, %2, %3;" : "=l"(d) : "l"(a), "l"(b), "l"(c));
    return d;
}

__device__ __forceinline__ float2 unpack2(ULL a) {
    unsigned lo, hi;
    asm("mov.b64 {%0, %1}, %2;" : "=r"(lo), "=r"(hi) : "l"(a));
    return make_float2(__uint_as_float(lo), __uint_as_float(hi));
}

// One-time (per replay, cheap) weight transpose into [k][o] layout so every CTA
// can copy weights into smem fully coalesced + conflict-free.
__global__ void transpose_kernel(const float* __restrict__ Wm,
                                 const float* __restrict__ Wa) {
    int i = blockIdx.x * blockDim.x + threadIdx.x;
    if (i < DOUT * K1) {
        int o = i / K1, k = i - o * K1;
        g_Wt_msg[k * DOUT + o] = Wm[i];
    }
    if (i < DOUT * K2) {
        int o = i / K2, k = i - o * K2;
        g_Wt_apply[k * DOUT + o] = Wa[i];
    }
}

// f32x2 dual-node GEMV core.
// Thread (og, ng) computes outputs o = 2*(og+16p)+{0,1}, p=0..3, for local nodes
// {2ng, 2ng+1}. Weight smem wt2[k*64 + op] holds {W[2op][k], W[2op+1][k]} — per k
// the 16 lanes (og) read 16 consecutive 64-bit words = one 128B conflict-free line.
// x smem is stored duplicated ({v,v}) so no per-iteration packing MOVs are needed.
template <int K, int XS>
__device__ __forceinline__ void gemv_dual(const ULL* __restrict__ wt2,
                                          const ULL* __restrict__ xs2,
                                          int og, int ng,
                                          ULL acc0[4], ULL acc1[4]) {
    const ULL* xa = xs2 + (2 * ng) * XS;
    const ULL* xb = xa + XS;
    const ULL* w  = wt2 + og;
#pragma unroll 8
    for (int k = 0; k < K; ++k) {
        ULL x0 = xa[k];
        ULL x1 = xb[k];
#pragma unroll
        for (int p = 0; p < 4; ++p) {
            ULL ww = w[k * 64 + 16 * p];
            acc0[p] = fma2(ww, x0, acc0[p]);
            acc1[p] = fma2(ww, x1, acc1[p]);
        }
    }
}

// Kernel 1: gather-sum neighbors + edge feats, then h_neigh = W_msg@[s;es]/16 + b_msg
__global__ void __launch_bounds__(TPB)
msg_kernel(const float* __restrict__ nfeats, const float* __restrict__ efeats,
           const float* __restrict__ b_msg, const int* __restrict__ src_idx) {
    extern __shared__ ULL smem[];
    ULL* wt2 = smem;                 // K1*64 f32x2
    ULL* xs2 = smem + K1 * 64;       // NB rows of XS1 f32x2 (duplicated x)

    const int tid  = threadIdx.x;
    const int base = blockIdx.x * NB;

    // coalesced, conflict-free weight stage-in (98 KB)
    {
        const float4* s = (const float4*)g_Wt_msg;
        float4*       d = (float4*)wt2;
#pragma unroll
        for (int i = 0; i < (K1 * DOUT / 4) / TPB; ++i)
            d[tid + i * TPB] = s[tid + i * TPB];
    }

    // gather phase: each warp owns 4 nodes; lane = float4 slot of the 128-dim row
    const int warp = tid >> 5, lane = tid & 31;
#pragma unroll
    for (int q = 0; q < 4; ++q) {
        int nd   = warp * 4 + q;
        int node = base + nd;
        if (node < N_NODES) {
            float4 aS = make_float4(0.f, 0.f, 0.f, 0.f);
            float4 aE = make_float4(0.f, 0.f, 0.f, 0.f);
            const int*    ip = src_idx + node * NNB;
            const float4* ef = (const float4*)(efeats + (size_t)node * NNB * EDIM);
#pragma unroll 4
            for (int j = 0; j < NNB; ++j) {
                int s = __ldg(ip + j);
                float4 a = __ldg((const float4*)nfeats + (size_t)s * (DIN / 4) + lane);
                aS.x += a.x; aS.y += a.y; aS.z += a.z; aS.w += a.w;
                if (lane < EDIM / 4) {
                    float4 b = __ldg(ef + j * (EDIM / 4) + lane);
                    aE.x += b.x; aE.y += b.y; aE.z += b.z; aE.w += b.w;
                }
            }
            const float inv = 1.f / 16.f;   // mean (cnt == 16 exactly, dst = repeat(arange,16))
            float2* xrow = (float2*)(xs2 + nd * XS1);
            int k0 = lane * 4;
            xrow[k0 + 0] = make_float2(aS.x * inv, aS.x * inv);
            xrow[k0 + 1] = make_float2(aS.y * inv, aS.y * inv);
            xrow[k0 + 2] = make_float2(aS.z * inv, aS.z * inv);
            xrow[k0 + 3] = make_float2(aS.w * inv, aS.w * inv);
            if (lane < EDIM / 4) {
                int ke = DIN + lane * 4;
                xrow[ke + 0] = make_float2(aE.x * inv, aE.x * inv);
                xrow[ke + 1] = make_float2(aE.y * inv, aE.y * inv);
                xrow[ke + 2] = make_float2(aE.z * inv, aE.z * inv);
                xrow[ke + 3] = make_float2(aE.w * inv, aE.w * inv);
            }
        }
    }
    __syncthreads();

    const int og = tid & 15, ng = tid >> 4;
    ULL acc0[4] = {0ull, 0ull, 0ull, 0ull};
    ULL acc1[4] = {0ull, 0ull, 0ull, 0ull};
    gemv_dual<K1, XS1>(wt2, xs2, og, ng, acc0, acc1);

    const float2* b2 = (const float2*)b_msg;
    int n0 = base + 2 * ng;
#pragma unroll
    for (int p = 0; p < 4; ++p) {
        int op = og + 16 * p;
        float2 bb = __ldg(b2 + op);
        if (n0 < N_NODES) {
            float2 v = unpack2(acc0[p]);
            v.x += bb.x; v.y += bb.y;
            ((float2*)(g_hneigh + (size_t)n0 * DOUT))[op] = v;
        }
        if (n0 + 1 < N_NODES) {
            float2 v = unpack2(acc1[p]);
            v.x += bb.x; v.y += bb.y;
            ((float2*)(g_hneigh + (size_t)(n0 + 1) * DOUT))[op] = v;
        }
    }
}

// Kernel 2: out = relu(W_apply @ [nfeats ; h_neigh] + b_apply)
__global__ void __launch_bounds__(TPB)
apply_kernel(const float* __restrict__ nfeats, const float* __restrict__ b_apply,
             float* __restrict__ out) {
    extern __shared__ ULL smem[];
    ULL* wt2 = smem;                 // K2*64
    ULL* xs2 = smem + K2 * 64;

    const int tid  = threadIdx.x;
    const int base = blockIdx.x * NB;

    {
        const float4* s = (const float4*)g_Wt_apply;
        float4*       d = (float4*)wt2;
#pragma unroll
        for (int i = 0; i < (K2 * DOUT / 4) / TPB; ++i)
            d[tid + i * TPB] = s[tid + i * TPB];
    }

    const int warp = tid >> 5, lane = tid & 31;
#pragma unroll
    for (int q = 0; q < 4; ++q) {
        int nd   = warp * 4 + q;
        int node = base + nd;
        if (node < N_NODES) {
            float4 a = __ldg((const float4*)(nfeats   + (size_t)node * DIN)  + lane);
            float4 h = __ldg((const float4*)(g_hneigh + (size_t)node * DOUT) + lane);
            float2* xrow = (float2*)(xs2 + nd * XS2);
            int k0 = lane * 4;
            xrow[k0 + 0] = make_float2(a.x, a.x);
            xrow[k0 + 1] = make_float2(a.y, a.y);
            xrow[k0 + 2] = make_float2(a.z, a.z);
            xrow[k0 + 3] = make_float2(a.w, a.w);
            int kh = DIN + lane * 4;
            xrow[kh + 0] = make_float2(h.x, h.x);
            xrow[kh + 1] = make_float2(h.y, h.y);
            xrow[kh + 2] = make_float2(h.z, h.z);
            xrow[kh + 3] = make_float2(h.w, h.w);
        }
    }
    __syncthreads();

    const int og = tid & 15, ng = tid >> 4;
    ULL acc0[4] = {0ull, 0ull, 0ull, 0ull};
    ULL acc1[4] = {0ull, 0ull, 0ull, 0ull};
    gemv_dual<K2, XS2>(wt2, xs2, og, ng, acc0, acc1);

    const float2* b2 = (const float2*)b_apply;
    int n0 = base + 2 * ng;
#pragma unroll
    for (int p = 0; p < 4; ++p) {
        int op = og + 16 * p;
        float2 bb = __ldg(b2 + op);
        if (n0 < N_NODES) {
            float2 v = unpack2(acc0[p]);
            v.x = fmaxf(v.x + bb.x, 0.f);
            v.y = fmaxf(v.y + bb.y, 0.f);
            ((float2*)(out + (size_t)n0 * DOUT))[op] = v;
        }
        if (n0 + 1 < N_NODES) {
            float2 v = unpack2(acc1[p]);
            v.x = fmaxf(v.x + bb.x, 0.f);
            v.y = fmaxf(v.y + bb.y, 0.f);
            ((float2*)(out + (size_t)(n0 + 1) * DOUT))[op] = v;
        }
    }
}

extern "C" void kernel_launch(void* const* d_in, const int* in_sizes, int n_in,
                              void* d_out, int out_size) {
    (void)in_sizes; (void)n_in; (void)out_size;
    const float* nfeats  = (const float*)d_in[0];
    const float* efeats  = (const float*)d_in[1];
    const float* W_msg   = (const float*)d_in[2];
    const float* b_msg   = (const float*)d_in[3];
    const float* W_apply = (const float*)d_in[4];
    const float* b_apply = (const float*)d_in[5];
    const int*   src_idx = (const int*)d_in[6];
    // d_in[7] = dst_idx: structurally repeat(arange(N),16) -> not needed
    float* out = (float*)d_out;

    const size_t smem1 = (size_t)(K1 * 64 + NB * XS1) * sizeof(ULL);  // 147,968 B
    const size_t smem2 = (size_t)(K2 * 64 + NB * XS2) * sizeof(ULL);  // 197,120 B
    cudaFuncSetAttribute(msg_kernel,   cudaFuncAttributeMaxDynamicSharedMemorySize, (int)smem1);
    cudaFuncSetAttribute(apply_kernel, cudaFuncAttributeMaxDynamicSharedMemorySize, (int)smem2);

    const int grid = (N_NODES + NB - 1) / NB;  // 1563
    transpose_kernel<<<(DOUT * K2 + TPB - 1) / TPB, TPB>>>(W_msg, W_apply);
    msg_kernel<<<grid, TPB, smem1>>>(nfeats, efeats, b_msg, src_idx);
    apply_kernel<<<grid, TPB, smem2>>>(nfeats, b_apply, out);
}

// round 4
// speedup vs baseline: 2.9830x; 2.9814x over previous
#include <cuda_runtime.h>
#include <cuda_bf16.h>
#include <cstdint>

#define N_NODES 50000
#define TILE    128
#define GRID    ((N_NODES + TILE - 1) / TILE)
#define TPB     512

// hi/lo pair-interleaved bf16 images: pair kp holds {hi(k,k+1), lo(k,k+1)} as 2x b32.
// Row strides chosen == 32 (mod 128) bytes -> all fragment LDS.64 are conflict-free.
#define WM_STRIDE 800      // [128 n][100 pairs] (96 real, K=192)
#define WA_STRIDE 1056     // [128 n][132 pairs] (128 real, K=256)
#define A1_STRIDE 800      // [128 m][100 pairs] (96 real)
#define A2_STRIDE 544      // [128 m][ 68 pairs] (64 real, half-K staging)
#define A1_OFF    102400   // phase1: Wmsg [0,102400) | A1 [102400,204800)
#define A2_OFF    135168   // phase2: Wapp [0,135168) | A2 [135168,204800)
#define SMEM_BYTES 204800

__device__ __align__(16) unsigned char g_Wm[128 * WM_STRIDE];
__device__ __align__(16) unsigned char g_Wa[128 * WA_STRIDE];

__device__ __forceinline__ void add4(float4& a, const float4 b) {
    a.x += b.x; a.y += b.y; a.z += b.z; a.w += b.w;
}
// split (a,b) into bf16 hi pair + bf16 lo pair (packed b32 each, lo16 = first elem)
__device__ __forceinline__ void pack2(float a, float b, uint32_t& hw, uint32_t& lw) {
    __nv_bfloat162 h = __floats2bfloat162_rn(a, b);
    hw = *reinterpret_cast<uint32_t*>(&h);
    float2 hf = __bfloat1622float2(h);
    __nv_bfloat162 l = __floats2bfloat162_rn(a - hf.x, b - hf.y);
    lw = *reinterpret_cast<uint32_t*>(&l);
}

__device__ __forceinline__ void mma_bf16(float c[4],
                                         uint32_t a0, uint32_t a1, uint32_t a2, uint32_t a3,
                                         uint32_t b0, uint32_t b1) {
    asm volatile(
        "mma.sync.aligned.m16n8k16.row.col.f32.bf16.bf16.f32 "
        "{%0,%1,%2,%3}, {%4,%5,%6,%7}, {%8,%9}, {%0,%1,%2,%3};"
        : "+f"(c[0]), "+f"(c[1]), "+f"(c[2]), "+f"(c[3])
        : "r"(a0), "r"(a1), "r"(a2), "r"(a3), "r"(b0), "r"(b1));
}

// fp32 W[o][k] row-major -> hi/lo pair-interleaved padded images (one-time, ~6us)
__global__ void prep_weights(const float* __restrict__ Wm, const float* __restrict__ Wa) {
    int i = blockIdx.x * blockDim.x + threadIdx.x;
    if (i >= 128 * 256) return;
    int o = i >> 8, k = i & 255;
    {
        float w = Wa[o * 256 + k];
        __nv_bfloat16 h = __float2bfloat16(w);
        __nv_bfloat16 l = __float2bfloat16(w - __bfloat162float(h));
        unsigned char* p = g_Wa + o * WA_STRIDE + (k >> 1) * 8 + (k & 1) * 2;
        *(__nv_bfloat16*)p = h;
        *(__nv_bfloat16*)(p + 4) = l;
    }
    if (k < 192) {
        float w = Wm[o * 192 + k];
        __nv_bfloat16 h = __float2bfloat16(w);
        __nv_bfloat16 l = __float2bfloat16(w - __bfloat162float(h));
        unsigned char* p = g_Wm + o * WM_STRIDE + (k >> 1) * 8 + (k & 1) * 2;
        *(__nv_bfloat16*)p = h;
        *(__nv_bfloat16*)(p + 4) = l;
    }
}

// split-bf16 GEMM tile: warp computes m16 (rows mrow..mrow+15) x n64 (cols nbase..+63).
// 3 products per k16-step: Ahi*Bhi + Ahi*Blo + Alo*Bhi.
template <int KSTEPS, int WSTRIDE, int ASTRIDE>
__device__ __forceinline__ void gemm_tile(const char* __restrict__ wbuf,
                                          const char* __restrict__ abuf,
                                          int mrow, int nbase, int gid, int tig,
                                          int wkp0, float acc[8][4]) {
#pragma unroll
    for (int kk = 0; kk < KSTEPS; ++kk) {
        const int kb = kk * 8;   // pair index base (8 pairs = k16)
        uint2 A0 = *(const uint2*)(abuf + (mrow + gid)     * ASTRIDE + (kb + tig) * 8);
        uint2 A1 = *(const uint2*)(abuf + (mrow + gid + 8) * ASTRIDE + (kb + tig) * 8);
        uint2 A2 = *(const uint2*)(abuf + (mrow + gid)     * ASTRIDE + (kb + 4 + tig) * 8);
        uint2 A3 = *(const uint2*)(abuf + (mrow + gid + 8) * ASTRIDE + (kb + 4 + tig) * 8);
#pragma unroll
        for (int t = 0; t < 8; ++t) {
            const char* wrow = wbuf + (nbase + t * 8 + gid) * WSTRIDE;
            uint2 B0 = *(const uint2*)(wrow + (wkp0 + kb + tig) * 8);
            uint2 B1 = *(const uint2*)(wrow + (wkp0 + kb + 4 + tig) * 8);
            mma_bf16(acc[t], A0.x, A1.x, A2.x, A3.x, B0.x, B1.x);  // hi*hi
            mma_bf16(acc[t], A0.x, A1.x, A2.x, A3.x, B0.y, B1.y);  // hi*lo
            mma_bf16(acc[t], A0.y, A1.y, A2.y, A3.y, B0.x, B1.x);  // lo*hi
        }
    }
}

__global__ void __launch_bounds__(TPB, 1)
sage_kernel(const float* __restrict__ nfeats, const float* __restrict__ efeats,
            const float* __restrict__ b_msg, const float* __restrict__ b_apply,
            const int* __restrict__ src_idx, float* __restrict__ out)
{
    extern __shared__ char sm[];
    const int tid  = threadIdx.x;
    const int wid  = tid >> 5;
    const int lane = tid & 31;
    const int gid  = lane >> 2;      // mma group id (row)
    const int tig  = lane & 3;       // thread in group (col pair)
    const int mrow  = (wid & 7) * 16;
    const int nbase = (wid >> 3) * 64;
    const int base  = blockIdx.x * TILE;

    // ---- phase 1: stage W_msg image + gather-sum into A1 ----
    {
        const float4* s = (const float4*)g_Wm;
        float4*       d = (float4*)sm;
#pragma unroll
        for (int i = 0; i < 13; ++i) {
            int idx = tid + i * TPB;
            if (idx < 128 * WM_STRIDE / 16) d[idx] = s[idx];
        }
    }
    {
        const float4* nf4 = (const float4*)nfeats;
        const float4* ef4 = (const float4*)efeats;
#pragma unroll 2
        for (int q = 0; q < 8; ++q) {
            const int nd = wid * 8 + q;
            const int node = base + nd;
            float4 a0 = {0,0,0,0}, a1 = {0,0,0,0}, ae = {0,0,0,0};
            if (node < N_NODES) {
                const int myidx = __ldg(src_idx + node * 16 + (lane & 15));
#pragma unroll
                for (int j = 0; j < 16; j += 2) {
                    const int s0 = __shfl_sync(0xffffffffu, myidx, j);
                    const int s1 = __shfl_sync(0xffffffffu, myidx, j + 1);
                    add4(a0, __ldg(nf4 + (size_t)s0 * 32 + lane));
                    add4(a1, __ldg(nf4 + (size_t)s1 * 32 + lane));
                    add4(ae, __ldg(ef4 + ((size_t)node * 16 + j + (lane >> 4)) * 16 + (lane & 15)));
                }
            }
            add4(a0, a1);
            ae.x += __shfl_down_sync(0xffffffffu, ae.x, 16);
            ae.y += __shfl_down_sync(0xffffffffu, ae.y, 16);
            ae.z += __shfl_down_sync(0xffffffffu, ae.z, 16);
            ae.w += __shfl_down_sync(0xffffffffu, ae.w, 16);
            const float inv = 0.0625f;   // mean over exactly 16 in-edges
            char* arow = sm + A1_OFF + nd * A1_STRIDE;
            uint32_t hw, lw;
            pack2(a0.x * inv, a0.y * inv, hw, lw);
            *(uint2*)(arow + (lane * 2)     * 8) = make_uint2(hw, lw);
            pack2(a0.z * inv, a0.w * inv, hw, lw);
            *(uint2*)(arow + (lane * 2 + 1) * 8) = make_uint2(hw, lw);
            if (lane < 16) {
                pack2(ae.x * inv, ae.y * inv, hw, lw);
                *(uint2*)(arow + (64 + lane * 2)     * 8) = make_uint2(hw, lw);
                pack2(ae.z * inv, ae.w * inv, hw, lw);
                *(uint2*)(arow + (64 + lane * 2 + 1) * 8) = make_uint2(hw, lw);
            }
        }
    }
    __syncthreads();

    // ---- GEMM1: D1 = A1 @ W_msg^T (K=192) ----
    float acc[8][4];
#pragma unroll
    for (int t = 0; t < 8; ++t)
#pragma unroll
        for (int j = 0; j < 4; ++j) acc[t][j] = 0.f;
    gemm_tile<12, WM_STRIDE, A1_STRIDE>(sm, sm + A1_OFF, mrow, nbase, gid, tig, 0, acc);
    __syncthreads();   // all warps done reading phase-1 smem

    // ---- h = D1 + b_msg -> A2 (h half of apply input); stage W_apply image ----
#pragma unroll
    for (int t = 0; t < 8; ++t) {
        const int n0 = nbase + t * 8 + 2 * tig;
        const float2 bm = __ldg((const float2*)(b_msg + n0));
        uint32_t hw, lw;
        pack2(acc[t][0] + bm.x, acc[t][1] + bm.y, hw, lw);
        *(uint2*)(sm + A2_OFF + (mrow + gid)     * A2_STRIDE + (n0 >> 1) * 8) = make_uint2(hw, lw);
        pack2(acc[t][2] + bm.x, acc[t][3] + bm.y, hw, lw);
        *(uint2*)(sm + A2_OFF + (mrow + gid + 8) * A2_STRIDE + (n0 >> 1) * 8) = make_uint2(hw, lw);
    }
    {
        const float4* s = (const float4*)g_Wa;
        float4*       d = (float4*)sm;
#pragma unroll
        for (int i = 0; i < 17; ++i) {
            int idx = tid + i * TPB;
            if (idx < 128 * WA_STRIDE / 16) d[idx] = s[idx];
        }
    }
    __syncthreads();

    // ---- GEMM2a: h half (W_apply k 128..255 -> pair offset 64) ----
#pragma unroll
    for (int t = 0; t < 8; ++t)
#pragma unroll
        for (int j = 0; j < 4; ++j) acc[t][j] = 0.f;
    gemm_tile<8, WA_STRIDE, A2_STRIDE>(sm, sm + A2_OFF, mrow, nbase, gid, tig, 64, acc);
    __syncthreads();   // done reading A2(h)

    // ---- restage A2 with nfeats rows (coalesced) ----
#pragma unroll 2
    for (int q = 0; q < 8; ++q) {
        const int nd = wid * 8 + q;
        const int node = base + nd;
        float4 v = {0,0,0,0};
        if (node < N_NODES) v = __ldg((const float4*)nfeats + (size_t)node * 32 + lane);
        char* arow = sm + A2_OFF + nd * A2_STRIDE;
        uint32_t hw, lw;
        pack2(v.x, v.y, hw, lw);
        *(uint2*)(arow + (lane * 2)     * 8) = make_uint2(hw, lw);
        pack2(v.z, v.w, hw, lw);
        *(uint2*)(arow + (lane * 2 + 1) * 8) = make_uint2(hw, lw);
    }
    __syncthreads();

    // ---- GEMM2b: nfeats half (W_apply k 0..127), accumulate ----
    gemm_tile<8, WA_STRIDE, A2_STRIDE>(sm, sm + A2_OFF, mrow, nbase, gid, tig, 0, acc);

    // ---- epilogue: relu(D2 + b_apply) -> out ----
#pragma unroll
    for (int t = 0; t < 8; ++t) {
        const int n0 = nbase + t * 8 + 2 * tig;
        const float2 ba = __ldg((const float2*)(b_apply + n0));
        const int r0 = base + mrow + gid;
        if (r0 < N_NODES) {
            float2 v;
            v.x = fmaxf(acc[t][0] + ba.x, 0.f);
            v.y = fmaxf(acc[t][1] + ba.y, 0.f);
            *(float2*)(out + (size_t)r0 * 128 + n0) = v;
        }
        const int r1 = r0 + 8;
        if (r1 < N_NODES) {
            float2 v;
            v.x = fmaxf(acc[t][2] + ba.x, 0.f);
            v.y = fmaxf(acc[t][3] + ba.y, 0.f);
            *(float2*)(out + (size_t)r1 * 128 + n0) = v;
        }
    }
}

extern "C" void kernel_launch(void* const* d_in, const int* in_sizes, int n_in,
                              void* d_out, int out_size) {
    (void)in_sizes; (void)n_in; (void)out_size;
    const float* nfeats  = (const float*)d_in[0];
    const float* efeats  = (const float*)d_in[1];
    const float* W_msg   = (const float*)d_in[2];
    const float* b_msg   = (const float*)d_in[3];
    const float* W_apply = (const float*)d_in[4];
    const float* b_apply = (const float*)d_in[5];
    const int*   src_idx = (const int*)d_in[6];
    float* out = (float*)d_out;

    cudaFuncSetAttribute(sage_kernel, cudaFuncAttributeMaxDynamicSharedMemorySize, SMEM_BYTES);

    prep_weights<<<128, 256>>>(W_msg, W_apply);
    sage_kernel<<<GRID, TPB, SMEM_BYTES>>>(nfeats, efeats, b_msg, b_apply, src_idx, out);
}